// round 14
// baseline (speedup 1.0000x reference)
#include <cuda_runtime.h>
#include <math.h>
#include <stdint.h>

#define J 23
#define BLK 128
#define VPT 2
#define TILE 256
#define NSTAGE 3

// dynamic smem byte offsets
#define SKIN_SZ  (TILE * J * 4)          /* 23552 */
#define V3_SZ    (TILE * 3 * 4)          /* 3072  */
#define OFF_SKIN(i) ((i) * SKIN_SZ)
#define OFF_VT(i)   (NSTAGE * SKIN_SZ + (i) * V3_SZ)
#define OFF_LA(i)   (NSTAGE * SKIN_SZ + NSTAGE * V3_SZ + (i) * V3_SZ)
#define OFF_RES(i)  (NSTAGE * SKIN_SZ + 2 * NSTAGE * V3_SZ + (i) * V3_SZ)
#define OFF_A       (NSTAGE * SKIN_SZ + 3 * NSTAGE * V3_SZ)   /* 98304 */
#define OFF_C       (OFF_A + J * 12 * 4)                      /* 99408 */
#define OFF_MBAR    (OFF_C + 16)                              /* 99424 */
#define SMEM_TOTAL  (OFF_MBAR + NSTAGE * 8)                   /* 99448 */

__device__ __constant__ int c_par[J] = {-1, 0, 1, 1, 3, 4, 5, 4, 7, 4, 9, 1, 11, 12, 13, 12, 15, 12, 17, 0, 19, 0, 21};

// scratch for the scalar fallback path (V % 4 != 0); unused in the main path
__device__ float g_A[J * 12 + 4];

__device__ __forceinline__ float tanh_fast(float x) {
    float r;
    asm("tanh.approx.f32 %0, %1;" : "=f"(r) : "f"(x));
    return r;
}

__device__ __forceinline__ unsigned long long evict_first_policy() {
    unsigned long long pol;
    asm("createpolicy.fractional.L2::evict_first.b64 %0, 1.0;" : "=l"(pol));
    return pol;
}

// ---------------- pose: executed by one full warp (lanes 0..31) -------------
__device__ __forceinline__ void pose_warp(
    int lane,
    const float* __restrict__ jr,
    const float* __restrict__ j0, const float* __restrict__ j1,
    const float* __restrict__ j2, const float* __restrict__ j3,
    const float* __restrict__ j4, const float* __restrict__ j5,
    const float* __restrict__ j12, const float* __restrict__ j13,
    const float* __restrict__ disp, const float* __restrict__ scl,
    const float* __restrict__ loc,
    float* outA, float* outC,          // A[J*12], C[4] = {c, ox, oy, oz}
    float* out, long long poseOff, long long jointsOff,
    long long scaleOff, long long dispOff, bool writeSmall)
{
    const float PI = 3.14159265358979323846f;
    int j = lane;
    float T[12];
    #pragma unroll
    for (int k = 0; k < 12; k++) T[k] = 0.f;

    if (j < J) {
        float amp = 0.f, sy = 1.f, sz = 1.f;
        const float* src = nullptr;
        switch (j) {
            case 0:  amp = PI / 2.f; src = j0;  break;
            case 1:  amp = PI / 4.f; src = j1;  break;
            case 2:  amp = PI / 9.f; src = j2;  break;
            case 3:  amp = PI / 3.f; src = j3;  break;
            case 11: amp = PI / 3.f; src = j3;  sy = -1.f; sz = -1.f; break;
            case 4:  amp = PI / 3.f; src = j4;  break;
            case 5:  amp = PI / 3.f; src = j5;  break;
            case 12: amp = PI / 3.f; src = j12; break;
            case 13: amp = PI / 3.f; src = j13; break;
        }
        float px = 0.f, py = 0.f, pz = 0.f;
        if (src) {
            px = amp * tanhf(src[0]);
            py = amp * sy * tanhf(src[1]);
            pz = amp * sz * tanhf(src[2]);
        }
        if (writeSmall) {
            out[poseOff + j * 3 + 0] = px;
            out[poseOff + j * 3 + 1] = py;
            out[poseOff + j * 3 + 2] = pz;
        }

        float ang = sqrtf(px * px + py * py + pz * pz + 1e-12f);
        float inv = 1.f / ang;
        float x = px * inv, y = py * inv, z = pz * inv;
        float s = sinf(ang), c = cosf(ang), t = 1.f - c;

        int p = c_par[j];
        float rx = jr[j * 3 + 0] - (p >= 0 ? jr[p * 3 + 0] : 0.f);
        float ry = jr[j * 3 + 1] - (p >= 0 ? jr[p * 3 + 1] : 0.f);
        float rz = jr[j * 3 + 2] - (p >= 0 ? jr[p * 3 + 2] : 0.f);

        T[0] = 1.f + t * (-(y * y + z * z));
        T[1] = -s * z + t * (x * y);
        T[2] =  s * y + t * (x * z);
        T[3] = rx;
        T[4] =  s * z + t * (x * y);
        T[5] = 1.f + t * (-(x * x + z * z));
        T[6] = -s * x + t * (y * z);
        T[7] = ry;
        T[8] = -s * y + t * (x * z);
        T[9] =  s * x + t * (y * z);
        T[10] = 1.f + t * (-(x * x + y * y));
        T[11] = rz;
    }

    float G[12];
    #pragma unroll
    for (int k = 0; k < 12; k++) G[k] = T[k];
    int a = (lane < J) ? c_par[lane] : -1;

    #pragma unroll
    for (int step = 0; step < 5; step++) {
        int srcLane = (a >= 0) ? a : 0;
        float L[12];
        #pragma unroll
        for (int k = 0; k < 12; k++)
            L[k] = __shfl_sync(0xffffffffu, T[k], srcLane);
        if (a >= 0) {
            float N[12];
            #pragma unroll
            for (int r = 0; r < 3; r++) {
                float l0 = L[r*4+0], l1 = L[r*4+1], l2 = L[r*4+2], l3 = L[r*4+3];
                N[r*4+0] = l0 * G[0] + l1 * G[4] + l2 * G[8];
                N[r*4+1] = l0 * G[1] + l1 * G[5] + l2 * G[9];
                N[r*4+2] = l0 * G[2] + l1 * G[6] + l2 * G[10];
                N[r*4+3] = l0 * G[3] + l1 * G[7] + l2 * G[11] + l3;
            }
            #pragma unroll
            for (int k = 0; k < 12; k++) G[k] = N[k];
            a = c_par[a];
        }
    }

    if (lane < J) {
        int jj = lane;
        float pjx = G[3], pjy = G[7], pjz = G[11];
        float jx = jr[jj*3+0], jy = jr[jj*3+1], jz = jr[jj*3+2];
        float tcx = G[0]*jx + G[1]*jy + G[2]*jz;
        float tcy = G[4]*jx + G[5]*jy + G[6]*jz;
        float tcz = G[8]*jx + G[9]*jy + G[10]*jz;
        G[3] -= tcx; G[7] -= tcy; G[11] -= tcz;
        #pragma unroll
        for (int k = 0; k < 12; k++) outA[jj * 12 + k] = G[k];

        float c0 = 0.0035f * scl[0];
        float ox = loc[0] + 0.1f * tanhf(disp[0]);
        float oy = loc[1] + 0.1f * tanhf(disp[1]);
        float oz = loc[2] + 0.1f * tanhf(disp[2]);
        if (writeSmall) {
            out[jointsOff + jj*3 + 0] = c0 * pjx + ox;
            out[jointsOff + jj*3 + 1] = c0 * pjy + oy;
            out[jointsOff + jj*3 + 2] = c0 * pjz + oz;
        }
        if (jj == 0) {
            outC[0] = c0; outC[1] = ox; outC[2] = oy; outC[3] = oz;
            if (writeSmall) {
                out[scaleOff] = scl[0];
                out[dispOff + 0] = disp[0];
                out[dispOff + 1] = disp[1];
                out[dispOff + 2] = disp[2];
            }
        }
    }
}

__device__ __forceinline__ void tma_load_tile(
    uint32_t smem_base, int s, uint32_t mb,
    const float* skin, const float* vt, const float* la,
    long long tbase, int nv, unsigned long long pol)
{
    asm volatile("mbarrier.arrive.expect_tx.shared.b64 _, [%0], %1;"
                 :: "r"(mb), "r"((uint32_t)(nv * (J + 6) * 4)) : "memory");
    asm volatile("cp.async.bulk.shared::cta.global.mbarrier::complete_tx::bytes.L2::cache_hint [%0], [%1], %2, [%3], %4;"
                 :: "r"(smem_base + OFF_SKIN(s)), "l"((const void*)(skin + tbase * J)),
                    "r"((uint32_t)(nv * J * 4)), "r"(mb), "l"(pol) : "memory");
    asm volatile("cp.async.bulk.shared::cta.global.mbarrier::complete_tx::bytes.L2::cache_hint [%0], [%1], %2, [%3], %4;"
                 :: "r"(smem_base + OFF_VT(s)), "l"((const void*)(vt + tbase * 3)),
                    "r"((uint32_t)(nv * 12)), "r"(mb), "l"(pol) : "memory");
    asm volatile("cp.async.bulk.shared::cta.global.mbarrier::complete_tx::bytes.L2::cache_hint [%0], [%1], %2, [%3], %4;"
                 :: "r"(smem_base + OFF_LA(s)), "l"((const void*)(la + tbase * 3)),
                    "r"((uint32_t)(nv * 12)), "r"(mb), "l"(pol) : "memory");
}

// ---------------- main persistent pipelined kernel --------------------------
__global__ __launch_bounds__(BLK, 2) void k_persist(
    const float* __restrict__ vt, const float* __restrict__ skin,
    const float* __restrict__ jr,
    const float* __restrict__ j0, const float* __restrict__ j1,
    const float* __restrict__ j2, const float* __restrict__ j3,
    const float* __restrict__ j4, const float* __restrict__ j5,
    const float* __restrict__ j12, const float* __restrict__ j13,
    const float* __restrict__ la, const float* __restrict__ disp,
    const float* __restrict__ scl, const float* __restrict__ loc,
    float* __restrict__ out,
    int V, int B, int ntiles,
    long long poseOff, long long jointsOff, long long scaleOff,
    long long dispOff, long long laOff)
{
    extern __shared__ __align__(128) unsigned char smem[];
    float* sA = (float*)(smem + OFF_A);
    float* sC = (float*)(smem + OFF_C);

    const int tid = threadIdx.x;
    const int G = gridDim.x;
    const uint32_t smem_base = (uint32_t)__cvta_generic_to_shared(smem);
    const uint32_t mbarBase = smem_base + OFF_MBAR;
    const unsigned long long pol = evict_first_policy();

    if (tid == 0) {
        #pragma unroll
        for (int k = 0; k < NSTAGE; k++)
            asm volatile("mbarrier.init.shared.b64 [%0], 1;" :: "r"(mbarBase + k * 8) : "memory");
    }
    __syncthreads();

    // prologue: issue TMA loads for the first NSTAGE tiles of this block
    if (tid == 0) {
        #pragma unroll
        for (int k = 0; k < NSTAGE; k++) {
            long long t = blockIdx.x + (long long)k * G;
            if (t < ntiles) {
                long long tbase = t * TILE;
                int nv = min(TILE, (int)(V - tbase));
                tma_load_tile(smem_base, k, mbarBase + k * 8, skin, vt, la, tbase, nv, pol);
            }
        }
    }

    // pose: once per block, overlapped with the prologue loads
    if (tid < 32) {
        pose_warp(tid, jr, j0, j1, j2, j3, j4, j5, j12, j13, disp, scl, loc,
                  sA, sC, out, poseOff, jointsOff, scaleOff, dispOff, blockIdx.x == 0);
    }
    __syncthreads();   // sA/sC visible

    const float cc = sC[0], oxc = sC[1], oyc = sC[2], ozc = sC[3];
    const long long stride = 3LL * V;

    int s = 0, ph = 0;
    for (long long t = blockIdx.x; t < ntiles; t += G) {
        const uint32_t mb = mbarBase + s * 8;

        // wait for this tile's data (HW-sleep try_wait); all threads wait the
        // mbarrier themselves, so no extra barrier is needed before reading
        asm volatile(
            "{\n\t.reg .pred P;\n"
            "WL%=:\n\t"
            "mbarrier.try_wait.parity.shared.b64 P, [%0], %1, 0x989680;\n\t"
            "@!P bra WL%=;\n\t}"
            :: "r"(mb), "r"(ph) : "memory");

        const long long tbase = t * TILE;
        const int nv = min(TILE, (int)(V - tbase));
        const float* sk  = (const float*)(smem + OFF_SKIN(s));
        const float* svt = (const float*)(smem + OFF_VT(s));
        const float* sla = (const float*)(smem + OFF_LA(s));
        float*       sre = (float*)      (smem + OFF_RES(s));

        // local_adjust passthrough first: STG.64s issue before the FMA chain
        {
            const float2* s2 = reinterpret_cast<const float2*>(sla);
            float2* d2 = reinterpret_cast<float2*>(out + laOff + tbase * 3);
            int n2 = (nv * 3) >> 1;
            for (int q = tid; q < n2; q += BLK) d2[q] = s2[q];
        }

        // ---- compute VPT vertices per thread ----
        float x[VPT], y[VPT], z[VPT], p0[VPT], p1[VPT], p2[VPT];
        bool val[VPT];
        #pragma unroll
        for (int i = 0; i < VPT; i++) {
            int lv = tid + i * BLK;
            val[i] = (lv < nv);
            int lc = val[i] ? lv : 0;
            float a0 = sla[lc*3+0], a1 = sla[lc*3+1], a2 = sla[lc*3+2];
            x[i] = fmaf(0.1f, tanh_fast(a0), svt[lc*3+0]);
            y[i] = fmaf(0.1f, tanh_fast(a1), svt[lc*3+1]);
            z[i] = fmaf(0.1f, tanh_fast(a2), svt[lc*3+2]);
            p0[i] = 0.f; p1[i] = 0.f; p2[i] = 0.f;
        }

        #pragma unroll
        for (int j = 0; j < J; j++) {
            float4 r0 = *reinterpret_cast<const float4*>(sA + j*12 + 0);
            float4 r1 = *reinterpret_cast<const float4*>(sA + j*12 + 4);
            float4 r2 = *reinterpret_cast<const float4*>(sA + j*12 + 8);
            #pragma unroll
            for (int i = 0; i < VPT; i++) {
                float wj = sk[(tid + i * BLK) * J + j];
                float d0 = fmaf(r0.x, x[i], fmaf(r0.y, y[i], fmaf(r0.z, z[i], r0.w)));
                float d1 = fmaf(r1.x, x[i], fmaf(r1.y, y[i], fmaf(r1.z, z[i], r1.w)));
                float d2 = fmaf(r2.x, x[i], fmaf(r2.y, y[i], fmaf(r2.z, z[i], r2.w)));
                p0[i] = fmaf(wj, d0, p0[i]);
                p1[i] = fmaf(wj, d1, p1[i]);
                p2[i] = fmaf(wj, d2, p2[i]);
            }
        }

        // drain our own NSTAGE-old bulk-store group AFTER the compute (the
        // drain overlaps the FMA chain above); the following barrier then
        // broadcasts "res buffer free" AND "all stage-s reads done" at once
        if (tid == 0)
            asm volatile("cp.async.bulk.wait_group %0;" :: "n"(NSTAGE - 1) : "memory");
        __syncthreads();

        #pragma unroll
        for (int i = 0; i < VPT; i++) {
            if (val[i]) {
                int lv = tid + i * BLK;
                sre[lv*3+0] = fmaf(cc, p0[i], oxc);
                sre[lv*3+1] = fmaf(cc, p1[i], oyc);
                sre[lv*3+2] = fmaf(cc, p2[i], ozc);
            }
        }

        __syncthreads();   // sRes[s] writes complete before bulk store / refill

        if (tid == 0) {
            // refill stage s with the tile NSTAGE iterations ahead
            long long tn = t + (long long)NSTAGE * G;
            if (tn < ntiles) {
                long long tb2 = tn * TILE;
                int nvn = min(TILE, (int)(V - tb2));
                tma_load_tile(smem_base, s, mb, skin, vt, la, tb2, nvn, pol);
            }

            // async bulk store of the B batch copies (streaming: evict_first)
            asm volatile("fence.proxy.async.shared::cta;" ::: "memory");
            uint32_t srcRes = smem_base + OFF_RES(s);
            uint32_t bytes = (uint32_t)(nv * 12);
            for (int b = 0; b < B; b++) {
                void* dst = out + (long long)b * stride + tbase * 3;
                asm volatile("cp.async.bulk.global.shared::cta.bulk_group.L2::cache_hint [%0], [%1], %2, %3;"
                             :: "l"(dst), "r"(srcRes), "r"(bytes), "l"(pol) : "memory");
            }
            asm volatile("cp.async.bulk.commit_group;" ::: "memory");
        }

        if (++s == NSTAGE) { s = 0; ph ^= 1; }
    }

    if (tid == 0)
        asm volatile("cp.async.bulk.wait_group 0;" ::: "memory");
    __syncthreads();
}

// ---------------- scalar fallback (only if V % 4 != 0) ----------------------
__global__ void k_pose_only(
    const float* __restrict__ jr,
    const float* __restrict__ j0, const float* __restrict__ j1,
    const float* __restrict__ j2, const float* __restrict__ j3,
    const float* __restrict__ j4, const float* __restrict__ j5,
    const float* __restrict__ j12, const float* __restrict__ j13,
    const float* __restrict__ disp, const float* __restrict__ scl,
    const float* __restrict__ loc,
    float* __restrict__ out,
    long long poseOff, long long jointsOff, long long scaleOff, long long dispOff)
{
    if (threadIdx.x < 32)
        pose_warp(threadIdx.x, jr, j0, j1, j2, j3, j4, j5, j12, j13, disp, scl, loc,
                  g_A, g_A + J * 12, out, poseOff, jointsOff, scaleOff, dispOff, true);
}

__global__ void k_naive(
    const float* __restrict__ vt, const float* __restrict__ skin,
    const float* __restrict__ la, float* __restrict__ out,
    int V, int B, long long laOff)
{
    long long v = blockIdx.x * (long long)blockDim.x + threadIdx.x;
    if (v >= V) return;
    float a0 = la[v*3+0], a1 = la[v*3+1], a2 = la[v*3+2];
    float x = vt[v*3+0] + 0.1f * tanhf(a0);
    float y = vt[v*3+1] + 0.1f * tanhf(a1);
    float z = vt[v*3+2] + 0.1f * tanhf(a2);
    float p0 = 0.f, p1 = 0.f, p2 = 0.f;
    #pragma unroll
    for (int j = 0; j < J; j++) {
        float wj = skin[v * J + j];
        const float* A = g_A + j * 12;
        p0 = fmaf(wj, fmaf(A[0], x, fmaf(A[1], y, fmaf(A[2],  z, A[3]))),  p0);
        p1 = fmaf(wj, fmaf(A[4], x, fmaf(A[5], y, fmaf(A[6],  z, A[7]))),  p1);
        p2 = fmaf(wj, fmaf(A[8], x, fmaf(A[9], y, fmaf(A[10], z, A[11]))), p2);
    }
    float cc = g_A[J*12+0];
    float o0 = fmaf(cc, p0, g_A[J*12+1]);
    float o1 = fmaf(cc, p1, g_A[J*12+2]);
    float o2 = fmaf(cc, p2, g_A[J*12+3]);
    long long stride = 3LL * V;
    for (int b = 0; b < B; b++) {
        long long o = (long long)b * stride + v * 3;
        out[o+0] = o0; out[o+1] = o1; out[o+2] = o2;
    }
    out[laOff + v*3 + 0] = a0;
    out[laOff + v*3 + 1] = a1;
    out[laOff + v*3 + 2] = a2;
}

extern "C" void kernel_launch(void* const* d_in, const int* in_sizes, int n_in,
                              void* d_out, int out_size)
{
    const float* vt   = (const float*)d_in[0];
    const float* skin = (const float*)d_in[1];
    const float* jr   = (const float*)d_in[2];
    const float* j0   = (const float*)d_in[3];
    const float* j1   = (const float*)d_in[4];
    const float* j2   = (const float*)d_in[5];
    const float* j3   = (const float*)d_in[6];
    const float* j4   = (const float*)d_in[7];
    const float* j5   = (const float*)d_in[8];
    const float* j12  = (const float*)d_in[9];
    const float* j13  = (const float*)d_in[10];
    const float* la   = (const float*)d_in[11];
    const float* disp = (const float*)d_in[12];
    const float* scl  = (const float*)d_in[13];
    const float* loc  = (const float*)d_in[14];

    int V = in_sizes[0] / 3;
    long long tail = 2LL * (3 * J) + 1 + 3;
    long long B = ((long long)out_size - tail - 3LL * V) / (3LL * V);

    long long poseOff   = B * 3LL * V;
    long long jointsOff = poseOff + 3 * J;
    long long scaleOff  = jointsOff + 3 * J;
    long long dispOff   = scaleOff + 1;
    long long laOff     = dispOff + 3;

    float* out = (float*)d_out;

    if ((V & 3) == 0) {
        int dev = 0, sms = 148;
        cudaGetDevice(&dev);
        cudaDeviceGetAttribute(&sms, cudaDevAttrMultiProcessorCount, dev);
        cudaFuncSetAttribute(k_persist, cudaFuncAttributeMaxDynamicSharedMemorySize, SMEM_TOTAL);
        int ntiles = (V + TILE - 1) / TILE;
        int grid = 2 * sms < ntiles ? 2 * sms : ntiles;
        k_persist<<<grid, BLK, SMEM_TOTAL>>>(vt, skin, jr, j0, j1, j2, j3, j4, j5,
                                             j12, j13, la, disp, scl, loc, out,
                                             V, (int)B, ntiles,
                                             poseOff, jointsOff, scaleOff, dispOff, laOff);
    } else {
        k_pose_only<<<1, 32>>>(jr, j0, j1, j2, j3, j4, j5, j12, j13, disp, scl, loc,
                               out, poseOff, jointsOff, scaleOff, dispOff);
        int blocks = (int)((V + 255) / 256);
        k_naive<<<blocks, 256>>>(vt, skin, la, out, V, (int)B, laOff);
    }
}

// round 15
// speedup vs baseline: 1.0136x; 1.0136x over previous
#include <cuda_runtime.h>
#include <math.h>
#include <stdint.h>

#define J 23
#define BLK 128
#define VPT 2
#define TILE 256
#define NSTAGE 3

// dynamic smem byte offsets
#define SKIN_SZ  (TILE * J * 4)          /* 23552 */
#define V3_SZ    (TILE * 3 * 4)          /* 3072  */
#define OFF_SKIN(i) ((i) * SKIN_SZ)
#define OFF_VT(i)   (NSTAGE * SKIN_SZ + (i) * V3_SZ)
#define OFF_LA(i)   (NSTAGE * SKIN_SZ + NSTAGE * V3_SZ + (i) * V3_SZ)
#define OFF_RES(i)  (NSTAGE * SKIN_SZ + 2 * NSTAGE * V3_SZ + (i) * V3_SZ)
#define OFF_A       (NSTAGE * SKIN_SZ + 3 * NSTAGE * V3_SZ)   /* 98304 */
#define OFF_C       (OFF_A + J * 12 * 4)                      /* 99408 */
#define OFF_MBAR    (OFF_C + 16)                              /* 99424 */
#define SMEM_TOTAL  (OFF_MBAR + NSTAGE * 8)                   /* 99448 */

__device__ __constant__ int c_par[J] = {-1, 0, 1, 1, 3, 4, 5, 4, 7, 4, 9, 1, 11, 12, 13, 12, 15, 12, 17, 0, 19, 0, 21};

// scratch for the scalar fallback path (V % 4 != 0); unused in the main path
__device__ float g_A[J * 12 + 4];

__device__ __forceinline__ float tanh_fast(float x) {
    float r;
    asm("tanh.approx.f32 %0, %1;" : "=f"(r) : "f"(x));
    return r;
}

__device__ __forceinline__ unsigned long long evict_first_policy() {
    unsigned long long pol;
    asm("createpolicy.fractional.L2::evict_first.b64 %0, 1.0;" : "=l"(pol));
    return pol;
}

__device__ __forceinline__ unsigned long long evict_last_policy() {
    unsigned long long pol;
    asm("createpolicy.fractional.L2::evict_last.b64 %0, 1.0;" : "=l"(pol));
    return pol;
}

__device__ __forceinline__ void stg_v2_hint(float2* ptr, float a, float b,
                                            unsigned long long pol) {
    asm volatile("st.global.L2::cache_hint.v2.f32 [%0], {%1, %2}, %3;"
                 :: "l"(ptr), "f"(a), "f"(b), "l"(pol) : "memory");
}

// ---------------- pose: executed by one full warp (lanes 0..31) -------------
__device__ __forceinline__ void pose_warp(
    int lane,
    const float* __restrict__ jr,
    const float* __restrict__ j0, const float* __restrict__ j1,
    const float* __restrict__ j2, const float* __restrict__ j3,
    const float* __restrict__ j4, const float* __restrict__ j5,
    const float* __restrict__ j12, const float* __restrict__ j13,
    const float* __restrict__ disp, const float* __restrict__ scl,
    const float* __restrict__ loc,
    float* outA, float* outC,          // A[J*12], C[4] = {c, ox, oy, oz}
    float* out, long long poseOff, long long jointsOff,
    long long scaleOff, long long dispOff, bool writeSmall)
{
    const float PI = 3.14159265358979323846f;
    int j = lane;
    float T[12];
    #pragma unroll
    for (int k = 0; k < 12; k++) T[k] = 0.f;

    if (j < J) {
        float amp = 0.f, sy = 1.f, sz = 1.f;
        const float* src = nullptr;
        switch (j) {
            case 0:  amp = PI / 2.f; src = j0;  break;
            case 1:  amp = PI / 4.f; src = j1;  break;
            case 2:  amp = PI / 9.f; src = j2;  break;
            case 3:  amp = PI / 3.f; src = j3;  break;
            case 11: amp = PI / 3.f; src = j3;  sy = -1.f; sz = -1.f; break;
            case 4:  amp = PI / 3.f; src = j4;  break;
            case 5:  amp = PI / 3.f; src = j5;  break;
            case 12: amp = PI / 3.f; src = j12; break;
            case 13: amp = PI / 3.f; src = j13; break;
        }
        float px = 0.f, py = 0.f, pz = 0.f;
        if (src) {
            px = amp * tanhf(src[0]);
            py = amp * sy * tanhf(src[1]);
            pz = amp * sz * tanhf(src[2]);
        }
        if (writeSmall) {
            out[poseOff + j * 3 + 0] = px;
            out[poseOff + j * 3 + 1] = py;
            out[poseOff + j * 3 + 2] = pz;
        }

        float ang = sqrtf(px * px + py * py + pz * pz + 1e-12f);
        float inv = 1.f / ang;
        float x = px * inv, y = py * inv, z = pz * inv;
        float s = sinf(ang), c = cosf(ang), t = 1.f - c;

        int p = c_par[j];
        float rx = jr[j * 3 + 0] - (p >= 0 ? jr[p * 3 + 0] : 0.f);
        float ry = jr[j * 3 + 1] - (p >= 0 ? jr[p * 3 + 1] : 0.f);
        float rz = jr[j * 3 + 2] - (p >= 0 ? jr[p * 3 + 2] : 0.f);

        T[0] = 1.f + t * (-(y * y + z * z));
        T[1] = -s * z + t * (x * y);
        T[2] =  s * y + t * (x * z);
        T[3] = rx;
        T[4] =  s * z + t * (x * y);
        T[5] = 1.f + t * (-(x * x + z * z));
        T[6] = -s * x + t * (y * z);
        T[7] = ry;
        T[8] = -s * y + t * (x * z);
        T[9] =  s * x + t * (y * z);
        T[10] = 1.f + t * (-(x * x + y * y));
        T[11] = rz;
    }

    float G[12];
    #pragma unroll
    for (int k = 0; k < 12; k++) G[k] = T[k];
    int a = (lane < J) ? c_par[lane] : -1;

    #pragma unroll
    for (int step = 0; step < 5; step++) {
        int srcLane = (a >= 0) ? a : 0;
        float L[12];
        #pragma unroll
        for (int k = 0; k < 12; k++)
            L[k] = __shfl_sync(0xffffffffu, T[k], srcLane);
        if (a >= 0) {
            float N[12];
            #pragma unroll
            for (int r = 0; r < 3; r++) {
                float l0 = L[r*4+0], l1 = L[r*4+1], l2 = L[r*4+2], l3 = L[r*4+3];
                N[r*4+0] = l0 * G[0] + l1 * G[4] + l2 * G[8];
                N[r*4+1] = l0 * G[1] + l1 * G[5] + l2 * G[9];
                N[r*4+2] = l0 * G[2] + l1 * G[6] + l2 * G[10];
                N[r*4+3] = l0 * G[3] + l1 * G[7] + l2 * G[11] + l3;
            }
            #pragma unroll
            for (int k = 0; k < 12; k++) G[k] = N[k];
            a = c_par[a];
        }
    }

    if (lane < J) {
        int jj = lane;
        float pjx = G[3], pjy = G[7], pjz = G[11];
        float jx = jr[jj*3+0], jy = jr[jj*3+1], jz = jr[jj*3+2];
        float tcx = G[0]*jx + G[1]*jy + G[2]*jz;
        float tcy = G[4]*jx + G[5]*jy + G[6]*jz;
        float tcz = G[8]*jx + G[9]*jy + G[10]*jz;
        G[3] -= tcx; G[7] -= tcy; G[11] -= tcz;
        #pragma unroll
        for (int k = 0; k < 12; k++) outA[jj * 12 + k] = G[k];

        float c0 = 0.0035f * scl[0];
        float ox = loc[0] + 0.1f * tanhf(disp[0]);
        float oy = loc[1] + 0.1f * tanhf(disp[1]);
        float oz = loc[2] + 0.1f * tanhf(disp[2]);
        if (writeSmall) {
            out[jointsOff + jj*3 + 0] = c0 * pjx + ox;
            out[jointsOff + jj*3 + 1] = c0 * pjy + oy;
            out[jointsOff + jj*3 + 2] = c0 * pjz + oz;
        }
        if (jj == 0) {
            outC[0] = c0; outC[1] = ox; outC[2] = oy; outC[3] = oz;
            if (writeSmall) {
                out[scaleOff] = scl[0];
                out[dispOff + 0] = disp[0];
                out[dispOff + 1] = disp[1];
                out[dispOff + 2] = disp[2];
            }
        }
    }
}

__device__ __forceinline__ void tma_load_tile(
    uint32_t smem_base, int s, uint32_t mb,
    const float* skin, const float* vt, const float* la,
    long long tbase, int nv, unsigned long long pol)
{
    asm volatile("mbarrier.arrive.expect_tx.shared.b64 _, [%0], %1;"
                 :: "r"(mb), "r"((uint32_t)(nv * (J + 6) * 4)) : "memory");
    asm volatile("cp.async.bulk.shared::cta.global.mbarrier::complete_tx::bytes.L2::cache_hint [%0], [%1], %2, [%3], %4;"
                 :: "r"(smem_base + OFF_SKIN(s)), "l"((const void*)(skin + tbase * J)),
                    "r"((uint32_t)(nv * J * 4)), "r"(mb), "l"(pol) : "memory");
    asm volatile("cp.async.bulk.shared::cta.global.mbarrier::complete_tx::bytes.L2::cache_hint [%0], [%1], %2, [%3], %4;"
                 :: "r"(smem_base + OFF_VT(s)), "l"((const void*)(vt + tbase * 3)),
                    "r"((uint32_t)(nv * 12)), "r"(mb), "l"(pol) : "memory");
    asm volatile("cp.async.bulk.shared::cta.global.mbarrier::complete_tx::bytes.L2::cache_hint [%0], [%1], %2, [%3], %4;"
                 :: "r"(smem_base + OFF_LA(s)), "l"((const void*)(la + tbase * 3)),
                    "r"((uint32_t)(nv * 12)), "r"(mb), "l"(pol) : "memory");
}

// ---------------- main persistent pipelined kernel --------------------------
__global__ __launch_bounds__(BLK, 2) void k_persist(
    const float* __restrict__ vt, const float* __restrict__ skin,
    const float* __restrict__ jr,
    const float* __restrict__ j0, const float* __restrict__ j1,
    const float* __restrict__ j2, const float* __restrict__ j3,
    const float* __restrict__ j4, const float* __restrict__ j5,
    const float* __restrict__ j12, const float* __restrict__ j13,
    const float* __restrict__ la, const float* __restrict__ disp,
    const float* __restrict__ scl, const float* __restrict__ loc,
    float* __restrict__ out,
    int V, int B, int ntiles,
    long long poseOff, long long jointsOff, long long scaleOff,
    long long dispOff, long long laOff)
{
    extern __shared__ __align__(128) unsigned char smem[];
    float* sA = (float*)(smem + OFF_A);
    float* sC = (float*)(smem + OFF_C);

    const int tid = threadIdx.x;
    const int G = gridDim.x;
    const uint32_t smem_base = (uint32_t)__cvta_generic_to_shared(smem);
    const uint32_t mbarBase = smem_base + OFF_MBAR;
    const unsigned long long polL = evict_first_policy();  // streaming reads
    const unsigned long long polS = evict_last_policy();   // L2-resident outputs

    if (tid == 0) {
        #pragma unroll
        for (int k = 0; k < NSTAGE; k++)
            asm volatile("mbarrier.init.shared.b64 [%0], 1;" :: "r"(mbarBase + k * 8) : "memory");
    }
    __syncthreads();

    // prologue: issue TMA loads for the first NSTAGE tiles of this block
    if (tid == 0) {
        #pragma unroll
        for (int k = 0; k < NSTAGE; k++) {
            long long t = blockIdx.x + (long long)k * G;
            if (t < ntiles) {
                long long tbase = t * TILE;
                int nv = min(TILE, (int)(V - tbase));
                tma_load_tile(smem_base, k, mbarBase + k * 8, skin, vt, la, tbase, nv, polL);
            }
        }
    }

    // pose: once per block, overlapped with the prologue loads
    if (tid < 32) {
        pose_warp(tid, jr, j0, j1, j2, j3, j4, j5, j12, j13, disp, scl, loc,
                  sA, sC, out, poseOff, jointsOff, scaleOff, dispOff, blockIdx.x == 0);
    }
    __syncthreads();   // sA/sC visible

    const float cc = sC[0], oxc = sC[1], oyc = sC[2], ozc = sC[3];
    const long long stride = 3LL * V;

    int s = 0, ph = 0;
    for (long long t = blockIdx.x; t < ntiles; t += G) {
        const uint32_t mb = mbarBase + s * 8;

        // wait for this tile's data (HW-sleep try_wait)
        asm volatile(
            "{\n\t.reg .pred P;\n"
            "WL%=:\n\t"
            "mbarrier.try_wait.parity.shared.b64 P, [%0], %1, 0x989680;\n\t"
            "@!P bra WL%=;\n\t}"
            :: "r"(mb), "r"(ph) : "memory");

        const long long tbase = t * TILE;
        const int nv = min(TILE, (int)(V - tbase));
        const float* sk  = (const float*)(smem + OFF_SKIN(s));
        const float* svt = (const float*)(smem + OFF_VT(s));
        const float* sla = (const float*)(smem + OFF_LA(s));
        float*       sre = (float*)      (smem + OFF_RES(s));

        // local_adjust passthrough first (evict_last: output stays L2-resident)
        {
            const float2* s2 = reinterpret_cast<const float2*>(sla);
            float2* d2 = reinterpret_cast<float2*>(out + laOff + tbase * 3);
            int n2 = (nv * 3) >> 1;
            for (int q = tid; q < n2; q += BLK) {
                float2 v = s2[q];
                stg_v2_hint(d2 + q, v.x, v.y, polS);
            }
        }

        // ---- compute VPT vertices per thread ----
        float x[VPT], y[VPT], z[VPT], p0[VPT], p1[VPT], p2[VPT];
        bool val[VPT];
        #pragma unroll
        for (int i = 0; i < VPT; i++) {
            int lv = tid + i * BLK;
            val[i] = (lv < nv);
            int lc = val[i] ? lv : 0;
            float a0 = sla[lc*3+0], a1 = sla[lc*3+1], a2 = sla[lc*3+2];
            x[i] = fmaf(0.1f, tanh_fast(a0), svt[lc*3+0]);
            y[i] = fmaf(0.1f, tanh_fast(a1), svt[lc*3+1]);
            z[i] = fmaf(0.1f, tanh_fast(a2), svt[lc*3+2]);
            p0[i] = 0.f; p1[i] = 0.f; p2[i] = 0.f;
        }

        #pragma unroll
        for (int j = 0; j < J; j++) {
            float4 r0 = *reinterpret_cast<const float4*>(sA + j*12 + 0);
            float4 r1 = *reinterpret_cast<const float4*>(sA + j*12 + 4);
            float4 r2 = *reinterpret_cast<const float4*>(sA + j*12 + 8);
            #pragma unroll
            for (int i = 0; i < VPT; i++) {
                float wj = sk[(tid + i * BLK) * J + j];
                float d0 = fmaf(r0.x, x[i], fmaf(r0.y, y[i], fmaf(r0.z, z[i], r0.w)));
                float d1 = fmaf(r1.x, x[i], fmaf(r1.y, y[i], fmaf(r1.z, z[i], r1.w)));
                float d2 = fmaf(r2.x, x[i], fmaf(r2.y, y[i], fmaf(r2.z, z[i], r2.w)));
                p0[i] = fmaf(wj, d0, p0[i]);
                p1[i] = fmaf(wj, d1, p1[i]);
                p2[i] = fmaf(wj, d2, p2[i]);
            }
        }

        // drain our own NSTAGE-old bulk-store group AFTER the compute (the
        // drain overlaps the FMA chain above); the following barrier then
        // broadcasts "res buffer free" AND "all stage-s reads done" at once
        if (tid == 0)
            asm volatile("cp.async.bulk.wait_group %0;" :: "n"(NSTAGE - 1) : "memory");
        __syncthreads();

        #pragma unroll
        for (int i = 0; i < VPT; i++) {
            if (val[i]) {
                int lv = tid + i * BLK;
                sre[lv*3+0] = fmaf(cc, p0[i], oxc);
                sre[lv*3+1] = fmaf(cc, p1[i], oyc);
                sre[lv*3+2] = fmaf(cc, p2[i], ozc);
            }
        }

        __syncthreads();   // sRes[s] writes complete before bulk store / refill

        if (tid == 0) {
            // refill stage s with the tile NSTAGE iterations ahead
            long long tn = t + (long long)NSTAGE * G;
            if (tn < ntiles) {
                long long tb2 = tn * TILE;
                int nvn = min(TILE, (int)(V - tb2));
                tma_load_tile(smem_base, s, mb, skin, vt, la, tb2, nvn, polL);
            }

            // async bulk store of the B batch copies (evict_last: L2-resident)
            asm volatile("fence.proxy.async.shared::cta;" ::: "memory");
            uint32_t srcRes = smem_base + OFF_RES(s);
            uint32_t bytes = (uint32_t)(nv * 12);
            for (int b = 0; b < B; b++) {
                void* dst = out + (long long)b * stride + tbase * 3;
                asm volatile("cp.async.bulk.global.shared::cta.bulk_group.L2::cache_hint [%0], [%1], %2, %3;"
                             :: "l"(dst), "r"(srcRes), "r"(bytes), "l"(polS) : "memory");
            }
            asm volatile("cp.async.bulk.commit_group;" ::: "memory");
        }

        if (++s == NSTAGE) { s = 0; ph ^= 1; }
    }

    if (tid == 0)
        asm volatile("cp.async.bulk.wait_group 0;" ::: "memory");
    __syncthreads();
}

// ---------------- scalar fallback (only if V % 4 != 0) ----------------------
__global__ void k_pose_only(
    const float* __restrict__ jr,
    const float* __restrict__ j0, const float* __restrict__ j1,
    const float* __restrict__ j2, const float* __restrict__ j3,
    const float* __restrict__ j4, const float* __restrict__ j5,
    const float* __restrict__ j12, const float* __restrict__ j13,
    const float* __restrict__ disp, const float* __restrict__ scl,
    const float* __restrict__ loc,
    float* __restrict__ out,
    long long poseOff, long long jointsOff, long long scaleOff, long long dispOff)
{
    if (threadIdx.x < 32)
        pose_warp(threadIdx.x, jr, j0, j1, j2, j3, j4, j5, j12, j13, disp, scl, loc,
                  g_A, g_A + J * 12, out, poseOff, jointsOff, scaleOff, dispOff, true);
}

__global__ void k_naive(
    const float* __restrict__ vt, const float* __restrict__ skin,
    const float* __restrict__ la, float* __restrict__ out,
    int V, int B, long long laOff)
{
    long long v = blockIdx.x * (long long)blockDim.x + threadIdx.x;
    if (v >= V) return;
    float a0 = la[v*3+0], a1 = la[v*3+1], a2 = la[v*3+2];
    float x = vt[v*3+0] + 0.1f * tanhf(a0);
    float y = vt[v*3+1] + 0.1f * tanhf(a1);
    float z = vt[v*3+2] + 0.1f * tanhf(a2);
    float p0 = 0.f, p1 = 0.f, p2 = 0.f;
    #pragma unroll
    for (int j = 0; j < J; j++) {
        float wj = skin[v * J + j];
        const float* A = g_A + j * 12;
        p0 = fmaf(wj, fmaf(A[0], x, fmaf(A[1], y, fmaf(A[2],  z, A[3]))),  p0);
        p1 = fmaf(wj, fmaf(A[4], x, fmaf(A[5], y, fmaf(A[6],  z, A[7]))),  p1);
        p2 = fmaf(wj, fmaf(A[8], x, fmaf(A[9], y, fmaf(A[10], z, A[11]))), p2);
    }
    float cc = g_A[J*12+0];
    float o0 = fmaf(cc, p0, g_A[J*12+1]);
    float o1 = fmaf(cc, p1, g_A[J*12+2]);
    float o2 = fmaf(cc, p2, g_A[J*12+3]);
    long long stride = 3LL * V;
    for (int b = 0; b < B; b++) {
        long long o = (long long)b * stride + v * 3;
        out[o+0] = o0; out[o+1] = o1; out[o+2] = o2;
    }
    out[laOff + v*3 + 0] = a0;
    out[laOff + v*3 + 1] = a1;
    out[laOff + v*3 + 2] = a2;
}

extern "C" void kernel_launch(void* const* d_in, const int* in_sizes, int n_in,
                              void* d_out, int out_size)
{
    const float* vt   = (const float*)d_in[0];
    const float* skin = (const float*)d_in[1];
    const float* jr   = (const float*)d_in[2];
    const float* j0   = (const float*)d_in[3];
    const float* j1   = (const float*)d_in[4];
    const float* j2   = (const float*)d_in[5];
    const float* j3   = (const float*)d_in[6];
    const float* j4   = (const float*)d_in[7];
    const float* j5   = (const float*)d_in[8];
    const float* j12  = (const float*)d_in[9];
    const float* j13  = (const float*)d_in[10];
    const float* la   = (const float*)d_in[11];
    const float* disp = (const float*)d_in[12];
    const float* scl  = (const float*)d_in[13];
    const float* loc  = (const float*)d_in[14];

    int V = in_sizes[0] / 3;
    long long tail = 2LL * (3 * J) + 1 + 3;
    long long B = ((long long)out_size - tail - 3LL * V) / (3LL * V);

    long long poseOff   = B * 3LL * V;
    long long jointsOff = poseOff + 3 * J;
    long long scaleOff  = jointsOff + 3 * J;
    long long dispOff   = scaleOff + 1;
    long long laOff     = dispOff + 3;

    float* out = (float*)d_out;

    if ((V & 3) == 0) {
        int dev = 0, sms = 148;
        cudaGetDevice(&dev);
        cudaDeviceGetAttribute(&sms, cudaDevAttrMultiProcessorCount, dev);
        cudaFuncSetAttribute(k_persist, cudaFuncAttributeMaxDynamicSharedMemorySize, SMEM_TOTAL);
        int ntiles = (V + TILE - 1) / TILE;
        int grid = 2 * sms < ntiles ? 2 * sms : ntiles;
        k_persist<<<grid, BLK, SMEM_TOTAL>>>(vt, skin, jr, j0, j1, j2, j3, j4, j5,
                                             j12, j13, la, disp, scl, loc, out,
                                             V, (int)B, ntiles,
                                             poseOff, jointsOff, scaleOff, dispOff, laOff);
    } else {
        k_pose_only<<<1, 32>>>(jr, j0, j1, j2, j3, j4, j5, j12, j13, disp, scl, loc,
                               out, poseOff, jointsOff, scaleOff, dispOff);
        int blocks = (int)((V + 255) / 256);
        k_naive<<<blocks, 256>>>(vt, skin, la, out, V, (int)B, laOff);
    }
}

// round 16
// speedup vs baseline: 1.0667x; 1.0523x over previous
#include <cuda_runtime.h>
#include <math.h>
#include <stdint.h>

#define J 23
#define BLK 128
#define VPT 2
#define TILE 256
#define NSTAGE 3

// dynamic smem byte offsets
#define SKIN_SZ  (TILE * J * 4)          /* 23552 */
#define V3_SZ    (TILE * 3 * 4)          /* 3072  */
#define OFF_SKIN(i) ((i) * SKIN_SZ)
#define OFF_VT(i)   (NSTAGE * SKIN_SZ + (i) * V3_SZ)
#define OFF_LA(i)   (NSTAGE * SKIN_SZ + NSTAGE * V3_SZ + (i) * V3_SZ)
#define OFF_RES(i)  (NSTAGE * SKIN_SZ + 2 * NSTAGE * V3_SZ + (i) * V3_SZ)
#define OFF_A       (NSTAGE * SKIN_SZ + 3 * NSTAGE * V3_SZ)   /* 98304 */
#define OFF_C       (OFF_A + J * 12 * 4)                      /* 99408 */
#define OFF_MBAR    (OFF_C + 16)                              /* 99424 */
#define SMEM_TOTAL  (OFF_MBAR + NSTAGE * 8)                   /* 99448 */

__device__ __constant__ int c_par[J] = {-1, 0, 1, 1, 3, 4, 5, 4, 7, 4, 9, 1, 11, 12, 13, 12, 15, 12, 17, 0, 19, 0, 21};

// scratch for the scalar fallback path (V % 4 != 0); unused in the main path
__device__ float g_A[J * 12 + 4];

__device__ __forceinline__ float tanh_fast(float x) {
    float r;
    asm("tanh.approx.f32 %0, %1;" : "=f"(r) : "f"(x));
    return r;
}

__device__ __forceinline__ unsigned long long evict_first_policy() {
    unsigned long long pol;
    asm("createpolicy.fractional.L2::evict_first.b64 %0, 1.0;" : "=l"(pol));
    return pol;
}

__device__ __forceinline__ unsigned long long evict_last_policy() {
    unsigned long long pol;
    asm("createpolicy.fractional.L2::evict_last.b64 %0, 1.0;" : "=l"(pol));
    return pol;
}

__device__ __forceinline__ void stg_v2_hint(float2* ptr, float a, float b,
                                            unsigned long long pol) {
    asm volatile("st.global.L2::cache_hint.v2.f32 [%0], {%1, %2}, %3;"
                 :: "l"(ptr), "f"(a), "f"(b), "l"(pol) : "memory");
}

// ---------------- pose: executed by one full warp (lanes 0..31) -------------
__device__ __forceinline__ void pose_warp(
    int lane,
    const float* __restrict__ jr,
    const float* __restrict__ j0, const float* __restrict__ j1,
    const float* __restrict__ j2, const float* __restrict__ j3,
    const float* __restrict__ j4, const float* __restrict__ j5,
    const float* __restrict__ j12, const float* __restrict__ j13,
    const float* __restrict__ disp, const float* __restrict__ scl,
    const float* __restrict__ loc,
    float* outA, float* outC,          // A[J*12], C[4] = {c, ox, oy, oz}
    float* out, long long poseOff, long long jointsOff,
    long long scaleOff, long long dispOff, bool writeSmall)
{
    const float PI = 3.14159265358979323846f;
    int j = lane;
    float T[12];
    #pragma unroll
    for (int k = 0; k < 12; k++) T[k] = 0.f;

    if (j < J) {
        float amp = 0.f, sy = 1.f, sz = 1.f;
        const float* src = nullptr;
        switch (j) {
            case 0:  amp = PI / 2.f; src = j0;  break;
            case 1:  amp = PI / 4.f; src = j1;  break;
            case 2:  amp = PI / 9.f; src = j2;  break;
            case 3:  amp = PI / 3.f; src = j3;  break;
            case 11: amp = PI / 3.f; src = j3;  sy = -1.f; sz = -1.f; break;
            case 4:  amp = PI / 3.f; src = j4;  break;
            case 5:  amp = PI / 3.f; src = j5;  break;
            case 12: amp = PI / 3.f; src = j12; break;
            case 13: amp = PI / 3.f; src = j13; break;
        }
        float px = 0.f, py = 0.f, pz = 0.f;
        if (src) {
            px = amp * tanhf(src[0]);
            py = amp * sy * tanhf(src[1]);
            pz = amp * sz * tanhf(src[2]);
        }
        if (writeSmall) {
            out[poseOff + j * 3 + 0] = px;
            out[poseOff + j * 3 + 1] = py;
            out[poseOff + j * 3 + 2] = pz;
        }

        float ang = sqrtf(px * px + py * py + pz * pz + 1e-12f);
        float inv = 1.f / ang;
        float x = px * inv, y = py * inv, z = pz * inv;
        float s = sinf(ang), c = cosf(ang), t = 1.f - c;

        int p = c_par[j];
        float rx = jr[j * 3 + 0] - (p >= 0 ? jr[p * 3 + 0] : 0.f);
        float ry = jr[j * 3 + 1] - (p >= 0 ? jr[p * 3 + 1] : 0.f);
        float rz = jr[j * 3 + 2] - (p >= 0 ? jr[p * 3 + 2] : 0.f);

        T[0] = 1.f + t * (-(y * y + z * z));
        T[1] = -s * z + t * (x * y);
        T[2] =  s * y + t * (x * z);
        T[3] = rx;
        T[4] =  s * z + t * (x * y);
        T[5] = 1.f + t * (-(x * x + z * z));
        T[6] = -s * x + t * (y * z);
        T[7] = ry;
        T[8] = -s * y + t * (x * z);
        T[9] =  s * x + t * (y * z);
        T[10] = 1.f + t * (-(x * x + y * y));
        T[11] = rz;
    }

    float G[12];
    #pragma unroll
    for (int k = 0; k < 12; k++) G[k] = T[k];
    int a = (lane < J) ? c_par[lane] : -1;

    #pragma unroll
    for (int step = 0; step < 5; step++) {
        int srcLane = (a >= 0) ? a : 0;
        float L[12];
        #pragma unroll
        for (int k = 0; k < 12; k++)
            L[k] = __shfl_sync(0xffffffffu, T[k], srcLane);
        if (a >= 0) {
            float N[12];
            #pragma unroll
            for (int r = 0; r < 3; r++) {
                float l0 = L[r*4+0], l1 = L[r*4+1], l2 = L[r*4+2], l3 = L[r*4+3];
                N[r*4+0] = l0 * G[0] + l1 * G[4] + l2 * G[8];
                N[r*4+1] = l0 * G[1] + l1 * G[5] + l2 * G[9];
                N[r*4+2] = l0 * G[2] + l1 * G[6] + l2 * G[10];
                N[r*4+3] = l0 * G[3] + l1 * G[7] + l2 * G[11] + l3;
            }
            #pragma unroll
            for (int k = 0; k < 12; k++) G[k] = N[k];
            a = c_par[a];
        }
    }

    if (lane < J) {
        int jj = lane;
        float pjx = G[3], pjy = G[7], pjz = G[11];
        float jx = jr[jj*3+0], jy = jr[jj*3+1], jz = jr[jj*3+2];
        float tcx = G[0]*jx + G[1]*jy + G[2]*jz;
        float tcy = G[4]*jx + G[5]*jy + G[6]*jz;
        float tcz = G[8]*jx + G[9]*jy + G[10]*jz;
        G[3] -= tcx; G[7] -= tcy; G[11] -= tcz;
        #pragma unroll
        for (int k = 0; k < 12; k++) outA[jj * 12 + k] = G[k];

        float c0 = 0.0035f * scl[0];
        float ox = loc[0] + 0.1f * tanhf(disp[0]);
        float oy = loc[1] + 0.1f * tanhf(disp[1]);
        float oz = loc[2] + 0.1f * tanhf(disp[2]);
        if (writeSmall) {
            out[jointsOff + jj*3 + 0] = c0 * pjx + ox;
            out[jointsOff + jj*3 + 1] = c0 * pjy + oy;
            out[jointsOff + jj*3 + 2] = c0 * pjz + oz;
        }
        if (jj == 0) {
            outC[0] = c0; outC[1] = ox; outC[2] = oy; outC[3] = oz;
            if (writeSmall) {
                out[scaleOff] = scl[0];
                out[dispOff + 0] = disp[0];
                out[dispOff + 1] = disp[1];
                out[dispOff + 2] = disp[2];
            }
        }
    }
}

// skin streams with polSkin (evict_first); vt/la try to pin with polVtLa (evict_last)
__device__ __forceinline__ void tma_load_tile(
    uint32_t smem_base, int s, uint32_t mb,
    const float* skin, const float* vt, const float* la,
    long long tbase, int nv,
    unsigned long long polSkin, unsigned long long polVtLa)
{
    asm volatile("mbarrier.arrive.expect_tx.shared.b64 _, [%0], %1;"
                 :: "r"(mb), "r"((uint32_t)(nv * (J + 6) * 4)) : "memory");
    asm volatile("cp.async.bulk.shared::cta.global.mbarrier::complete_tx::bytes.L2::cache_hint [%0], [%1], %2, [%3], %4;"
                 :: "r"(smem_base + OFF_SKIN(s)), "l"((const void*)(skin + tbase * J)),
                    "r"((uint32_t)(nv * J * 4)), "r"(mb), "l"(polSkin) : "memory");
    asm volatile("cp.async.bulk.shared::cta.global.mbarrier::complete_tx::bytes.L2::cache_hint [%0], [%1], %2, [%3], %4;"
                 :: "r"(smem_base + OFF_VT(s)), "l"((const void*)(vt + tbase * 3)),
                    "r"((uint32_t)(nv * 12)), "r"(mb), "l"(polVtLa) : "memory");
    asm volatile("cp.async.bulk.shared::cta.global.mbarrier::complete_tx::bytes.L2::cache_hint [%0], [%1], %2, [%3], %4;"
                 :: "r"(smem_base + OFF_LA(s)), "l"((const void*)(la + tbase * 3)),
                    "r"((uint32_t)(nv * 12)), "r"(mb), "l"(polVtLa) : "memory");
}

// ---------------- main persistent pipelined kernel --------------------------
__global__ __launch_bounds__(BLK, 2) void k_persist(
    const float* __restrict__ vt, const float* __restrict__ skin,
    const float* __restrict__ jr,
    const float* __restrict__ j0, const float* __restrict__ j1,
    const float* __restrict__ j2, const float* __restrict__ j3,
    const float* __restrict__ j4, const float* __restrict__ j5,
    const float* __restrict__ j12, const float* __restrict__ j13,
    const float* __restrict__ la, const float* __restrict__ disp,
    const float* __restrict__ scl, const float* __restrict__ loc,
    float* __restrict__ out,
    int V, int B, int ntiles,
    long long poseOff, long long jointsOff, long long scaleOff,
    long long dispOff, long long laOff)
{
    extern __shared__ __align__(128) unsigned char smem[];
    float* sA = (float*)(smem + OFF_A);
    float* sC = (float*)(smem + OFF_C);

    const int tid = threadIdx.x;
    const int G = gridDim.x;
    const uint32_t smem_base = (uint32_t)__cvta_generic_to_shared(smem);
    const uint32_t mbarBase = smem_base + OFF_MBAR;
    const unsigned long long polL = evict_first_policy();  // skin: pure stream
    const unsigned long long polR = evict_last_policy();   // vt/la: try L2-resident
    const unsigned long long polS = evict_last_policy();   // outputs

    if (tid == 0) {
        #pragma unroll
        for (int k = 0; k < NSTAGE; k++)
            asm volatile("mbarrier.init.shared.b64 [%0], 1;" :: "r"(mbarBase + k * 8) : "memory");
    }
    __syncthreads();

    // prologue: issue TMA loads for the first NSTAGE tiles of this block
    if (tid == 0) {
        #pragma unroll
        for (int k = 0; k < NSTAGE; k++) {
            long long t = blockIdx.x + (long long)k * G;
            if (t < ntiles) {
                long long tbase = t * TILE;
                int nv = min(TILE, (int)(V - tbase));
                tma_load_tile(smem_base, k, mbarBase + k * 8, skin, vt, la, tbase, nv, polL, polR);
            }
        }
    }

    // pose: once per block, overlapped with the prologue loads
    if (tid < 32) {
        pose_warp(tid, jr, j0, j1, j2, j3, j4, j5, j12, j13, disp, scl, loc,
                  sA, sC, out, poseOff, jointsOff, scaleOff, dispOff, blockIdx.x == 0);
    }
    __syncthreads();   // sA/sC visible

    const float cc = sC[0], oxc = sC[1], oyc = sC[2], ozc = sC[3];
    const long long stride = 3LL * V;

    int s = 0, ph = 0;
    for (long long t = blockIdx.x; t < ntiles; t += G) {
        const uint32_t mb = mbarBase + s * 8;

        // wait for this tile's data (HW-sleep try_wait)
        asm volatile(
            "{\n\t.reg .pred P;\n"
            "WL%=:\n\t"
            "mbarrier.try_wait.parity.shared.b64 P, [%0], %1, 0x989680;\n\t"
            "@!P bra WL%=;\n\t}"
            :: "r"(mb), "r"(ph) : "memory");

        const long long tbase = t * TILE;
        const int nv = min(TILE, (int)(V - tbase));
        const float* sk  = (const float*)(smem + OFF_SKIN(s));
        const float* svt = (const float*)(smem + OFF_VT(s));
        const float* sla = (const float*)(smem + OFF_LA(s));
        float*       sre = (float*)      (smem + OFF_RES(s));

        // local_adjust passthrough first (evict_last hint on output)
        {
            const float2* s2 = reinterpret_cast<const float2*>(sla);
            float2* d2 = reinterpret_cast<float2*>(out + laOff + tbase * 3);
            int n2 = (nv * 3) >> 1;
            for (int q = tid; q < n2; q += BLK) {
                float2 v = s2[q];
                stg_v2_hint(d2 + q, v.x, v.y, polS);
            }
        }

        // ---- compute VPT vertices per thread ----
        float x[VPT], y[VPT], z[VPT], p0[VPT], p1[VPT], p2[VPT];
        bool val[VPT];
        #pragma unroll
        for (int i = 0; i < VPT; i++) {
            int lv = tid + i * BLK;
            val[i] = (lv < nv);
            int lc = val[i] ? lv : 0;
            float a0 = sla[lc*3+0], a1 = sla[lc*3+1], a2 = sla[lc*3+2];
            x[i] = fmaf(0.1f, tanh_fast(a0), svt[lc*3+0]);
            y[i] = fmaf(0.1f, tanh_fast(a1), svt[lc*3+1]);
            z[i] = fmaf(0.1f, tanh_fast(a2), svt[lc*3+2]);
            p0[i] = 0.f; p1[i] = 0.f; p2[i] = 0.f;
        }

        #pragma unroll
        for (int j = 0; j < J; j++) {
            float4 r0 = *reinterpret_cast<const float4*>(sA + j*12 + 0);
            float4 r1 = *reinterpret_cast<const float4*>(sA + j*12 + 4);
            float4 r2 = *reinterpret_cast<const float4*>(sA + j*12 + 8);
            #pragma unroll
            for (int i = 0; i < VPT; i++) {
                float wj = sk[(tid + i * BLK) * J + j];
                float d0 = fmaf(r0.x, x[i], fmaf(r0.y, y[i], fmaf(r0.z, z[i], r0.w)));
                float d1 = fmaf(r1.x, x[i], fmaf(r1.y, y[i], fmaf(r1.z, z[i], r1.w)));
                float d2 = fmaf(r2.x, x[i], fmaf(r2.y, y[i], fmaf(r2.z, z[i], r2.w)));
                p0[i] = fmaf(wj, d0, p0[i]);
                p1[i] = fmaf(wj, d1, p1[i]);
                p2[i] = fmaf(wj, d2, p2[i]);
            }
        }

        // drain our own NSTAGE-old bulk-store group AFTER the compute (the
        // drain overlaps the FMA chain above); the following barrier then
        // broadcasts "res buffer free" AND "all stage-s reads done" at once
        if (tid == 0)
            asm volatile("cp.async.bulk.wait_group %0;" :: "n"(NSTAGE - 1) : "memory");
        __syncthreads();

        #pragma unroll
        for (int i = 0; i < VPT; i++) {
            if (val[i]) {
                int lv = tid + i * BLK;
                sre[lv*3+0] = fmaf(cc, p0[i], oxc);
                sre[lv*3+1] = fmaf(cc, p1[i], oyc);
                sre[lv*3+2] = fmaf(cc, p2[i], ozc);
            }
        }

        __syncthreads();   // sRes[s] writes complete before bulk store / refill

        if (tid == 0) {
            // refill stage s with the tile NSTAGE iterations ahead
            long long tn = t + (long long)NSTAGE * G;
            if (tn < ntiles) {
                long long tb2 = tn * TILE;
                int nvn = min(TILE, (int)(V - tb2));
                tma_load_tile(smem_base, s, mb, skin, vt, la, tb2, nvn, polL, polR);
            }

            // async bulk store of the B batch copies
            asm volatile("fence.proxy.async.shared::cta;" ::: "memory");
            uint32_t srcRes = smem_base + OFF_RES(s);
            uint32_t bytes = (uint32_t)(nv * 12);
            for (int b = 0; b < B; b++) {
                void* dst = out + (long long)b * stride + tbase * 3;
                asm volatile("cp.async.bulk.global.shared::cta.bulk_group.L2::cache_hint [%0], [%1], %2, %3;"
                             :: "l"(dst), "r"(srcRes), "r"(bytes), "l"(polS) : "memory");
            }
            asm volatile("cp.async.bulk.commit_group;" ::: "memory");
        }

        if (++s == NSTAGE) { s = 0; ph ^= 1; }
    }

    if (tid == 0)
        asm volatile("cp.async.bulk.wait_group 0;" ::: "memory");
    __syncthreads();
}

// ---------------- scalar fallback (only if V % 4 != 0) ----------------------
__global__ void k_pose_only(
    const float* __restrict__ jr,
    const float* __restrict__ j0, const float* __restrict__ j1,
    const float* __restrict__ j2, const float* __restrict__ j3,
    const float* __restrict__ j4, const float* __restrict__ j5,
    const float* __restrict__ j12, const float* __restrict__ j13,
    const float* __restrict__ disp, const float* __restrict__ scl,
    const float* __restrict__ loc,
    float* __restrict__ out,
    long long poseOff, long long jointsOff, long long scaleOff, long long dispOff)
{
    if (threadIdx.x < 32)
        pose_warp(threadIdx.x, jr, j0, j1, j2, j3, j4, j5, j12, j13, disp, scl, loc,
                  g_A, g_A + J * 12, out, poseOff, jointsOff, scaleOff, dispOff, true);
}

__global__ void k_naive(
    const float* __restrict__ vt, const float* __restrict__ skin,
    const float* __restrict__ la, float* __restrict__ out,
    int V, int B, long long laOff)
{
    long long v = blockIdx.x * (long long)blockDim.x + threadIdx.x;
    if (v >= V) return;
    float a0 = la[v*3+0], a1 = la[v*3+1], a2 = la[v*3+2];
    float x = vt[v*3+0] + 0.1f * tanhf(a0);
    float y = vt[v*3+1] + 0.1f * tanhf(a1);
    float z = vt[v*3+2] + 0.1f * tanhf(a2);
    float p0 = 0.f, p1 = 0.f, p2 = 0.f;
    #pragma unroll
    for (int j = 0; j < J; j++) {
        float wj = skin[v * J + j];
        const float* A = g_A + j * 12;
        p0 = fmaf(wj, fmaf(A[0], x, fmaf(A[1], y, fmaf(A[2],  z, A[3]))),  p0);
        p1 = fmaf(wj, fmaf(A[4], x, fmaf(A[5], y, fmaf(A[6],  z, A[7]))),  p1);
        p2 = fmaf(wj, fmaf(A[8], x, fmaf(A[9], y, fmaf(A[10], z, A[11]))), p2);
    }
    float cc = g_A[J*12+0];
    float o0 = fmaf(cc, p0, g_A[J*12+1]);
    float o1 = fmaf(cc, p1, g_A[J*12+2]);
    float o2 = fmaf(cc, p2, g_A[J*12+3]);
    long long stride = 3LL * V;
    for (int b = 0; b < B; b++) {
        long long o = (long long)b * stride + v * 3;
        out[o+0] = o0; out[o+1] = o1; out[o+2] = o2;
    }
    out[laOff + v*3 + 0] = a0;
    out[laOff + v*3 + 1] = a1;
    out[laOff + v*3 + 2] = a2;
}

extern "C" void kernel_launch(void* const* d_in, const int* in_sizes, int n_in,
                              void* d_out, int out_size)
{
    const float* vt   = (const float*)d_in[0];
    const float* skin = (const float*)d_in[1];
    const float* jr   = (const float*)d_in[2];
    const float* j0   = (const float*)d_in[3];
    const float* j1   = (const float*)d_in[4];
    const float* j2   = (const float*)d_in[5];
    const float* j3   = (const float*)d_in[6];
    const float* j4   = (const float*)d_in[7];
    const float* j5   = (const float*)d_in[8];
    const float* j12  = (const float*)d_in[9];
    const float* j13  = (const float*)d_in[10];
    const float* la   = (const float*)d_in[11];
    const float* disp = (const float*)d_in[12];
    const float* scl  = (const float*)d_in[13];
    const float* loc  = (const float*)d_in[14];

    int V = in_sizes[0] / 3;
    long long tail = 2LL * (3 * J) + 1 + 3;
    long long B = ((long long)out_size - tail - 3LL * V) / (3LL * V);

    long long poseOff   = B * 3LL * V;
    long long jointsOff = poseOff + 3 * J;
    long long scaleOff  = jointsOff + 3 * J;
    long long dispOff   = scaleOff + 1;
    long long laOff     = dispOff + 3;

    float* out = (float*)d_out;

    if ((V & 3) == 0) {
        int dev = 0, sms = 148;
        cudaGetDevice(&dev);
        cudaDeviceGetAttribute(&sms, cudaDevAttrMultiProcessorCount, dev);
        cudaFuncSetAttribute(k_persist, cudaFuncAttributeMaxDynamicSharedMemorySize, SMEM_TOTAL);
        int ntiles = (V + TILE - 1) / TILE;
        int grid = 2 * sms < ntiles ? 2 * sms : ntiles;
        k_persist<<<grid, BLK, SMEM_TOTAL>>>(vt, skin, jr, j0, j1, j2, j3, j4, j5,
                                             j12, j13, la, disp, scl, loc, out,
                                             V, (int)B, ntiles,
                                             poseOff, jointsOff, scaleOff, dispOff, laOff);
    } else {
        k_pose_only<<<1, 32>>>(jr, j0, j1, j2, j3, j4, j5, j12, j13, disp, scl, loc,
                               out, poseOff, jointsOff, scaleOff, dispOff);
        int blocks = (int)((V + 255) / 256);
        k_naive<<<blocks, 256>>>(vt, skin, la, out, V, (int)B, laOff);
    }
}